// round 11
// baseline (speedup 1.0000x reference)
#include <cuda_runtime.h>

// CGCoupler: out[n, ro[m]] += x1[n, r1[m]] * x2[n, r2[m]] * cg[m]
//
// SINGLE persistent kernel.
// Stage 0 (per-CTA, redundant, deterministic): build the path tables in smem.
//   Paths: index arrays are path-major runs (r1/r2/ro consecutive, cg equal)
//   over a dense channel dim ns=0..deg-1; run starts partition [0,M) so
//   deg_i = start_{i+1}-start_i. One block scan -> ordered starts; bin by
//   output base ro_0; canonical in-bin sort (deg desc, r1, r2); per-column
//   {start|ns<<16, eff}. All in smem; scratch overlaps the tile buffers.
// Stage 1 (persistent tiles, cp.async double buffer): rows stored contiguously
//   in smem; tile t+1 copied via cp.async while tile t computes. Thread owns
//   2 output columns; gathers are lane-consecutive LDS.32 (conflict-free);
//   path records are warp-uniform broadcasts.

#define N_BATCH 16384
#define RPT     4
#define TPB     320
#define OCC     4
#define NSM     148
#define P_SMEM  512
#define NSORT   512

__device__ __forceinline__ void cp16(void* s, const void* g) {
    unsigned sa = (unsigned)__cvta_generic_to_shared(s);
    asm volatile("cp.async.cg.shared.global [%0], [%1], 16;\n" :: "r"(sa), "l"(g));
}
__device__ __forceinline__ void cp_commit() {
    asm volatile("cp.async.commit_group;\n");
}
__device__ __forceinline__ void cp_wait1() {
    asm volatile("cp.async.wait_group 1;\n" ::: "memory");
}
__device__ __forceinline__ void cp_wait0() {
    asm volatile("cp.async.wait_group 0;\n" ::: "memory");
}

__device__ __forceinline__ int block_incl_scan(int v, int tid) {
    __shared__ int ws[32];
    int lane = tid & 31, wid = tid >> 5;
    __syncthreads();
    #pragma unroll
    for (int d = 1; d < 32; d <<= 1) {
        int t = __shfl_up_sync(0xffffffffu, v, d);
        if (lane >= d) v += t;
    }
    if (lane == 31) ws[wid] = v;
    __syncthreads();
    if (wid == 0) {
        int w = (lane < TPB / 32) ? ws[lane] : 0;
        #pragma unroll
        for (int d = 1; d < 32; d <<= 1) {
            int t = __shfl_up_sync(0xffffffffu, w, d);
            if (lane >= d) w += t;
        }
        ws[lane] = w;
    }
    __syncthreads();
    return v + (wid > 0 ? ws[wid - 1] : 0);
}

__global__ void __launch_bounds__(TPB, OCC)
cg_kernel(const float* __restrict__ x1, const float* __restrict__ x2,
          float* __restrict__ out,
          const void* r1v, const void* r2v, const void* rov,
          const float* __restrict__ cgv_, int M,
          int rep_dim, int out_dim, int ntiles, int region_bytes) {
    extern __shared__ char smraw[];
    // persistent tables live after the buffer/scratch region
    uint4* pts = (uint4*)(smraw + region_bytes);      // P_SMEM paths (binned+sorted)
    uint2* ci  = (uint2*)(pts + P_SMEM);              // out_dim col info
    // prep scratch (overlaps tile buffers; dead after prep)
    uint4* praw = (uint4*)smraw;                      // NSORT
    int*   sp   = (int*)(praw + NSORT);               // NSORT+1
    int*   pro  = sp + NSORT + 1;                     // NSORT
    int*   cnt  = pro + NSORT;                        // out_dim
    int*   stt  = cnt + out_dim;                      // out_dim
    int*   cur  = stt + out_dim;                      // out_dim
    __shared__ int s_is64, s_np;

    int tid = threadIdx.x;

    // ================= Stage 0: per-CTA prep (redundant, deterministic) ======
    if (tid < 32) {
        const unsigned* w = (const unsigned*)r1v;
        int nw = M < 512 ? M : 512;
        int bad = 0;
        for (int i = 1 + 2 * tid; i < nw; i += 64) bad |= (w[i] != 0u);
        unsigned any = __ballot_sync(0xffffffffu, bad != 0);
        if (tid == 0) s_is64 = (any == 0u);
    }
    __syncthreads();
    int is64 = s_is64;
    const int*       r132 = (const int*)r1v;  const long long* r164 = (const long long*)r1v;
    const int*       r232 = (const int*)r2v;  const long long* r264 = (const long long*)r2v;
    const int*       ro32 = (const int*)rov;  const long long* ro64 = (const long long*)rov;
    const unsigned*  cgu  = (const unsigned*)cgv_;
    #define IDX1(m) (is64 ? (int)r164[m] : r132[m])
    #define IDX2(m) (is64 ? (int)r264[m] : r232[m])
    #define IDXO(m) (is64 ? (int)ro64[m] : ro32[m])
    #define ISSTART(m) ((m) == 0 || \
        !(IDX1((m) - 1) + 1 == IDX1(m) && IDX2((m) - 1) + 1 == IDX2(m) && \
          IDXO((m) - 1) + 1 == IDXO(m) && cgu[(m) - 1] == cgu[m]))

    // Phase A: ordered compaction of run starts (one block scan)
    {
        int C = (M + TPB - 1) / TPB;
        int beg = tid * C;
        int end = beg + C; if (end > M) end = M;
        int cl = 0;
        for (int m = beg; m < end; m++) cl += ISSTART(m);
        int incl = block_incl_scan(cl, tid);
        int off = incl - cl;
        for (int m = beg; m < end; m++)
            if (ISSTART(m)) { if (off < NSORT) sp[off] = m; off++; }
        if (tid == TPB - 1) s_np = incl;
    }
    __syncthreads();
    int P = s_np;
    if (P > NSORT) P = NSORT;                   // safety; expected P ~ 150
    if (tid == 0) sp[P] = M;
    __syncthreads();

    // Phase B: materialize paths in position order
    for (int p = tid; p < P; p += TPB) {
        int s = sp[p];
        praw[p] = make_uint4((unsigned)IDX1(s), (unsigned)IDX2(s),
                             cgu[s], (unsigned)(sp[p + 1] - s));
        pro[p] = IDXO(s);
    }
    for (int i = tid; i < out_dim; i += TPB) cnt[i] = 0;
    for (int i = tid; i < P_SMEM; i += TPB) pts[i] = make_uint4(0u, 0u, 0u, 0u);
    __syncthreads();

    // Phase C: bin by ro_0, exclusive scan, scatter into pts
    for (int p = tid; p < P; p += TPB) atomicAdd(&cnt[pro[p]], 1);
    __syncthreads();
    {
        int CH = (out_dim + TPB - 1) / TPB;
        int cb = tid * CH;
        int local = 0;
        for (int i = 0; i < CH; i++) { int idx = cb + i; if (idx < out_dim) local += cnt[idx]; }
        int incl = block_incl_scan(local, tid);
        int run = incl - local;
        for (int i = 0; i < CH; i++) {
            int idx = cb + i;
            if (idx < out_dim) { stt[idx] = run; cur[idx] = run; run += cnt[idx]; }
        }
    }
    __syncthreads();
    for (int p = tid; p < P; p += TPB) {
        int pos = atomicAdd(&cur[pro[p]], 1);
        pts[pos] = praw[p];
    }
    __syncthreads();

    // Phase D: canonical in-bin insertion sort (deg DESC, r1 ASC, r2 ASC)
    for (int b = tid; b < out_dim; b += TPB) {
        int c0 = cnt[b];
        if (c0 > 1) {
            int s0 = stt[b];
            for (int i = 1; i < c0; i++) {
                uint4 key = pts[s0 + i];
                int j = i - 1;
                while (j >= 0) {
                    uint4 q = pts[s0 + j];
                    bool keyFirst = (key.w > q.w) ||
                                    (key.w == q.w && (key.x < q.x ||
                                     (key.x == q.x && key.y < q.y)));
                    if (!keyFirst) break;
                    pts[s0 + j + 1] = q;
                    j--;
                }
                pts[s0 + j + 1] = key;
            }
        }
    }
    __syncthreads();

    // Phase E: per-column info
    for (int c = tid; c < out_dim; c += TPB) {
        int b = c;
        while (b >= 0 && cnt[b] == 0) b--;
        uint2 info = make_uint2(0u, 0u);
        if (b >= 0) {
            int c0 = cnt[b], s0 = stt[b], ns = c - b, eff = 0;
            while (eff < c0 && (int)pts[s0 + eff].w > ns) eff++;
            if (eff > 0)
                info = make_uint2((unsigned)s0 | ((unsigned)ns << 16), (unsigned)eff);
        }
        ci[c] = info;
    }
    __syncthreads();   // tables final; scratch region is now free for buffers
    #undef ISSTART
    #undef IDX1
    #undef IDX2
    #undef IDXO

    // hoisted per-thread column info
    int o0 = tid, o1 = tid + TPB;
    uint2 c0 = (o0 < out_dim) ? ci[o0] : make_uint2(0u, 0u);
    uint2 c1 = (o1 < out_dim) ? ci[o1] : make_uint2(0u, 0u);
    int s0 = (int)(c0.x & 0xffffu), ne0 = (int)c0.y; int ns0 = (int)(c0.x >> 16);
    int s1 = (int)(c1.x & 0xffffu), ne1 = (int)c1.y; int ns1 = (int)(c1.x >> 16);

    // ================= Stage 1: persistent tiles, cp.async double buffer =====
    float* xb = (float*)smraw;                  // buf[2], each 8*rep_dim floats
    int buff = 8 * rep_dim;                     // floats per buffer
    int bid = blockIdx.x, stride = gridDim.x;
    bool vec_ok = ((rep_dim & 3) == 0);
    int nchrow = rep_dim >> 2;                  // 16B chunks per row
    int nch = 8 * nchrow;                       // chunks per tile (x1+x2, RPT rows)

    // stage tile into buffer b (cp.async fast path / scalar fallback)
    auto stage = [&](int b, int t) {
        float* dst = xb + b * buff;
        if (vec_ok) {
            for (int c = tid; c < nch; c += TPB) {
                int arr = c / (4 * nchrow);
                int rem = c - arr * 4 * nchrow;
                int row = rem / nchrow;
                int off = (rem - row * nchrow) << 2;
                const float* g = (arr ? x2 : x1)
                               + ((size_t)t * RPT + row) * rep_dim + off;
                cp16(dst + arr * 4 * rep_dim + row * rep_dim + off, g);
            }
            cp_commit();
        } else {
            for (int i = tid; i < 8 * rep_dim; i += TPB) {
                int arr = i / (4 * rep_dim);
                int rem = i - arr * 4 * rep_dim;
                int row = rem / rep_dim;
                int off = rem - row * rep_dim;
                dst[i] = (arr ? x2 : x1)[((size_t)t * RPT + row) * rep_dim + off];
            }
        }
    };

    if (bid < ntiles) stage(0, bid);
    int ph = 0;
    for (int t = bid; t < ntiles; t += stride) {
        int tn = t + stride;
        if (tn < ntiles) { stage(ph ^ 1, tn); if (vec_ok) cp_wait1(); }
        else             { if (vec_ok) cp_wait0(); }
        __syncthreads();                        // buffer ph complete & visible

        const float* A = xb + ph * buff;        // x1 rows r..r+3, contiguous
        const float* B = A + 4 * rep_dim;       // x2 rows r..r+3
        float a00 = 0.f, a01 = 0.f, a02 = 0.f, a03 = 0.f;
        float a10 = 0.f, a11 = 0.f, a12 = 0.f, a13 = 0.f;
        #pragma unroll 2
        for (int j = 0; j < ne0; j++) {
            uint4 p = pts[s0 + j];              // warp-uniform broadcast
            float cgc = __uint_as_float(p.z);
            int ia = p.x + ns0, ib = p.y + ns0; // lane-consecutive: conflict-free
            a00 = fmaf(A[ia] * B[ib], cgc, a00);
            a01 = fmaf(A[ia + rep_dim] * B[ib + rep_dim], cgc, a01);
            a02 = fmaf(A[ia + 2 * rep_dim] * B[ib + 2 * rep_dim], cgc, a02);
            a03 = fmaf(A[ia + 3 * rep_dim] * B[ib + 3 * rep_dim], cgc, a03);
        }
        #pragma unroll 2
        for (int j = 0; j < ne1; j++) {
            uint4 p = pts[s1 + j];
            float cgc = __uint_as_float(p.z);
            int ia = p.x + ns1, ib = p.y + ns1;
            a10 = fmaf(A[ia] * B[ib], cgc, a10);
            a11 = fmaf(A[ia + rep_dim] * B[ib + rep_dim], cgc, a11);
            a12 = fmaf(A[ia + 2 * rep_dim] * B[ib + 2 * rep_dim], cgc, a12);
            a13 = fmaf(A[ia + 3 * rep_dim] * B[ib + 3 * rep_dim], cgc, a13);
        }
        int r = t * RPT;
        if (o0 < out_dim) {
            float* ob = out + (size_t)r * out_dim + o0;
            ob[0] = a00; ob[out_dim] = a01;
            ob[2 * (size_t)out_dim] = a02; ob[3 * (size_t)out_dim] = a03;
        }
        if (o1 < out_dim) {
            float* ob = out + (size_t)r * out_dim + o1;
            ob[0] = a10; ob[out_dim] = a11;
            ob[2 * (size_t)out_dim] = a12; ob[3 * (size_t)out_dim] = a13;
        }
        // generic fallback for out_dim > 2*TPB (not taken for this shape)
        for (int obase = 2 * TPB; obase < out_dim; obase += TPB) {
            int o = obase + tid;
            if (o < out_dim) {
                uint2 c = ci[o];
                int s = (int)(c.x & 0xffffu), ne = (int)c.y;
                int ns = (int)(c.x >> 16);
                float b0 = 0.f, b1 = 0.f, b2 = 0.f, b3 = 0.f;
                for (int j = 0; j < ne; j++) {
                    uint4 p = pts[s + j];
                    float cgc = __uint_as_float(p.z);
                    int ia = p.x + ns, ib = p.y + ns;
                    b0 = fmaf(A[ia] * B[ib], cgc, b0);
                    b1 = fmaf(A[ia + rep_dim] * B[ib + rep_dim], cgc, b1);
                    b2 = fmaf(A[ia + 2 * rep_dim] * B[ib + 2 * rep_dim], cgc, b2);
                    b3 = fmaf(A[ia + 3 * rep_dim] * B[ib + 3 * rep_dim], cgc, b3);
                }
                float* ob = out + (size_t)r * out_dim + o;
                ob[0] = b0; ob[out_dim] = b1;
                ob[2 * (size_t)out_dim] = b2; ob[3 * (size_t)out_dim] = b3;
            }
        }
        __syncthreads();                        // done reading buffer ph
        ph ^= 1;
    }
}

extern "C" void kernel_launch(void* const* d_in, const int* in_sizes, int n_in,
                              void* d_out, int out_size) {
    const float* x1 = (const float*)d_in[0];
    const float* x2 = (const float*)d_in[1];
    const float* cg = (const float*)d_in[2];
    const void*  r1 = d_in[3];
    const void*  r2 = d_in[4];
    const void*  ro = d_in[5];
    int M = in_sizes[2];
    int rep_dim = in_sizes[0] / N_BATCH;
    int out_dim = out_size / N_BATCH;
    int ntiles  = N_BATCH / RPT;

    // smem layout: [ region = max(buffers, prep scratch) ][ pts ][ ci ]
    size_t bufbytes = (size_t)2 * 8 * rep_dim * 4;
    size_t scratch  = (size_t)NSORT * 16 + (size_t)(NSORT + 1) * 4
                    + (size_t)NSORT * 4 + (size_t)3 * out_dim * 4;
    size_t region = bufbytes > scratch ? bufbytes : scratch;
    region = (region + 15) & ~(size_t)15;
    size_t smem = region + (size_t)P_SMEM * 16 + (size_t)out_dim * 8;

    cudaFuncSetAttribute(cg_kernel,
                         cudaFuncAttributeMaxDynamicSharedMemorySize, 220 * 1024);
    int grid = NSM * OCC;
    if (grid > ntiles) grid = ntiles;
    cg_kernel<<<grid, TPB, smem>>>(x1, x2, (float*)d_out, r1, r2, ro, cg, M,
                                   rep_dim, out_dim, ntiles, (int)region);
}